// round 15
// baseline (speedup 1.0000x reference)
#include <cuda_runtime.h>
#include <cuda_fp16.h>

#define D 128
#define MAXN 40000
#define MAXE 640000

// ---------------- scratch (zero-initialized device globals; no allocation) ----
__device__ float g_deg[MAXN];        // accumulates sum(ea) per dst; reset by k_scan
__device__ int   g_cnt[MAXN];        // in-degree; reset by k_scan
__device__ float g_dinv[MAXN];       // rsqrt(1 + sum(ea))
__device__ int   g_offs[MAXN + 1];
__device__ int   g_cursor[MAXN];
__device__ __align__(16) int2   g_edge[MAXE];      // {src, nrm bits}
__device__ __align__(16) __half g_Hh[MAXN * D];    // h = A @ W, fp16 (gathered)
__device__ __align__(16) float  g_G[MAXN * D];     // post-agg activations (fp32)

// ---------------- tf32 helpers -------------------------------------------------
__device__ __forceinline__ unsigned f2tf32(float x) {
    unsigned r;
    asm("cvt.rna.tf32.f32 %0, %1;" : "=r"(r) : "f"(x));
    return r;
}
__device__ __forceinline__ void mma_tf32(float* c, const unsigned* a,
                                         unsigned b0, unsigned b1) {
    asm volatile(
        "mma.sync.aligned.m16n8k8.row.col.f32.tf32.tf32.f32 "
        "{%0,%1,%2,%3}, {%4,%5,%6,%7}, {%8,%9}, {%0,%1,%2,%3};\n"
        : "+f"(c[0]), "+f"(c[1]), "+f"(c[2]), "+f"(c[3])
        : "r"(a[0]), "r"(a[1]), "r"(a[2]), "r"(a[3]), "r"(b0), "r"(b1));
}

// ---------------- per-block dtype probe ----------------------------------------
// Reads the first 256 words as int64 (2KB, broadcast L2 hit). int32 data
// reinterpreted merges random pairs -> >= 2^32 with overwhelming probability.
__device__ __forceinline__ int probe_is64(const void* ei) {
    const long long* p = (const long long*)ei;
    long long v = p[threadIdx.x & 255];
    bool bad = (v < 0 || v >= MAXN);
    return __syncthreads_or(bad) ? 0 : 1;
}
__device__ __forceinline__ int edge_at(const void* ei, long long idx, int is64) {
    if (is64) return (int)((const long long*)ei)[idx];
    return ((const int*)ei)[idx];
}

// ---------------- preprocessing (R13-proven shapes, k_init removed) -----------
__global__ void k_deg(const void* __restrict__ ei,
                      const float* __restrict__ ea, int e) {
    int is64 = probe_is64(ei);
    int i = blockIdx.x * blockDim.x + threadIdx.x;
    if (i < e) {
        int dst = edge_at(ei, (long long)e + i, is64);
        atomicAdd(&g_deg[dst], ea[i]);
        atomicAdd(&g_cnt[dst], 1);
    }
}

// Single-block scan of g_cnt -> g_offs/g_cursor; emits g_dinv; resets deg/cnt.
__global__ void k_scan(int n) {
    __shared__ int s[1024];
    int t = threadIdx.x;
    int ch = (n + 1023) >> 10;
    int base = t * ch;
    int sum = 0;
    for (int j = 0; j < ch; j++) {
        int idx = base + j;
        if (idx < n) {
            g_dinv[idx] = rsqrtf(1.0f + g_deg[idx]);   // +1 = self-loop weight
            g_deg[idx] = 0.0f;                          // reset for next call
            sum += g_cnt[idx];
        }
    }
    s[t] = sum;
    __syncthreads();
    for (int off = 1; off < 1024; off <<= 1) {
        int v = (t >= off) ? s[t - off] : 0;
        __syncthreads();
        s[t] += v;
        __syncthreads();
    }
    if (t == 1023) g_offs[n] = s[1023];
    int prefix = (t == 0) ? 0 : s[t - 1];
    for (int j = 0; j < ch; j++) {
        int idx = base + j;
        if (idx < n) {
            g_offs[idx]   = prefix;
            g_cursor[idx] = prefix;
            prefix += g_cnt[idx];
            g_cnt[idx] = 0;                             // reset for next call
        }
    }
}

__global__ void k_fill(const void* __restrict__ ei,
                       const float* __restrict__ ea, int e) {
    int is64 = probe_is64(ei);
    int i = blockIdx.x * blockDim.x + threadIdx.x;
    if (i < e) {
        int src = edge_at(ei, i, is64);
        int dst = edge_at(ei, (long long)e + i, is64);
        float nrm = g_dinv[src] * ea[i] * g_dinv[dst];
        int pos = atomicAdd(&g_cursor[dst], 1);
        g_edge[pos] = make_int2(src, __float_as_int(nrm));
    }
}

// ---------------- tf32 tensor-core GEMM (R13 proven, fp16 epilogue) ----------
template <int USE_G>
__global__ void __launch_bounds__(256) k_gemm(const float* __restrict__ Ain,
                                              const float* __restrict__ W,
                                              int nrows) {
    const float* __restrict__ A = USE_G ? (const float*)g_G : Ain;
    extern __shared__ unsigned wf[];   // [ks16][nf16][lane32][2] tf32

    int tid = threadIdx.x;
    for (int s = tid; s < 16 * 16 * 32; s += 256) {
        int lane = s & 31;
        int nf = (s >> 5) & 15;
        int ks = s >> 9;
        int k = ks * 8 + (lane & 3);
        int nn = nf * 8 + (lane >> 2);
        unsigned lo = f2tf32(W[k * D + nn]);
        unsigned hi = f2tf32(W[(k + 4) * D + nn]);
        *(uint2*)&wf[s * 2] = make_uint2(lo, hi);
    }
    __syncthreads();

    int wid = tid >> 5, lane = tid & 31;
    int ly = lane >> 2, lx = lane & 3;
    int rowbase = blockIdx.x * 128 + wid * 16;
    int ra = rowbase + ly;     if (ra >= nrows) ra = nrows - 1;
    int rb = rowbase + ly + 8; if (rb >= nrows) rb = nrows - 1;
    const float* pa = A + (size_t)ra * D + lx;
    const float* pb = A + (size_t)rb * D + lx;

    float acc[16][4];
#pragma unroll
    for (int nf = 0; nf < 16; nf++)
#pragma unroll
        for (int j = 0; j < 4; j++) acc[nf][j] = 0.0f;

    unsigned a_cur[4], a_nxt[4];
    a_cur[0] = f2tf32(pa[0]); a_cur[1] = f2tf32(pb[0]);
    a_cur[2] = f2tf32(pa[4]); a_cur[3] = f2tf32(pb[4]);

#pragma unroll
    for (int ks = 0; ks < 16; ks++) {
        if (ks < 15) {
            int k0 = (ks + 1) * 8;
            a_nxt[0] = f2tf32(pa[k0]);     a_nxt[1] = f2tf32(pb[k0]);
            a_nxt[2] = f2tf32(pa[k0 + 4]); a_nxt[3] = f2tf32(pb[k0 + 4]);
        }
        const unsigned* wrow = &wf[(ks * 16 * 32 + lane) * 2];
#pragma unroll
        for (int nf = 0; nf < 16; nf++) {
            uint2 b = *(const uint2*)&wrow[nf * 64];
            mma_tf32(acc[nf], a_cur, b.x, b.y);
        }
#pragma unroll
        for (int j = 0; j < 4; j++) a_cur[j] = a_nxt[j];
    }

    int r1 = rowbase + ly;
    int r2 = rowbase + ly + 8;
#pragma unroll
    for (int nf = 0; nf < 16; nf++) {
        int c = nf * 8 + lx * 2;
        if (r1 < nrows)
            *(__half2*)&g_Hh[(size_t)r1 * D + c] = __floats2half2_rn(acc[nf][0], acc[nf][1]);
        if (r2 < nrows)
            *(__half2*)&g_Hh[(size_t)r2 * D + c] = __floats2half2_rn(acc[nf][2], acc[nf][3]);
    }
}

// ---------------- aggregation (R13 proven): warp/node, fp16 gather, 8-unroll --
template <int LN>
__global__ void k_agg(const float* __restrict__ bias,
                      const float* __restrict__ gamma, const float* __restrict__ beta,
                      float* __restrict__ outp, int n) {
    int w = (blockIdx.x * blockDim.x + threadIdx.x) >> 5;
    int lane = threadIdx.x & 31;
    if (w >= n) return;

    const uint2* __restrict__ Hh = (const uint2*)g_Hh;   // 32 uint2 per row
    float di = g_dinv[w];
    float selfw = di * di;

    uint2 vs = __ldg(&Hh[(size_t)w * 32 + lane]);
    float2 s0f = __half22float2(*(__half2*)&vs.x);
    float2 s1f = __half22float2(*(__half2*)&vs.y);
    float4 acc = make_float4(s0f.x * selfw, s0f.y * selfw,
                             s1f.x * selfw, s1f.y * selfw);

    int ib = g_offs[w];
    int ie = g_offs[w + 1];
    int i = ib;
    for (; i + 8 <= ie; i += 8) {
        int2 ed[8];
        uint2 v[8];
#pragma unroll
        for (int j = 0; j < 8; j++) ed[j] = g_edge[i + j];
#pragma unroll
        for (int j = 0; j < 8; j++)
            v[j] = __ldg(&Hh[(size_t)ed[j].x * 32 + lane]);
#pragma unroll
        for (int j = 0; j < 8; j++) {
            float wgt = __int_as_float(ed[j].y);
            float2 p0 = __half22float2(*(__half2*)&v[j].x);
            float2 p1 = __half22float2(*(__half2*)&v[j].y);
            acc.x += p0.x * wgt; acc.y += p0.y * wgt;
            acc.z += p1.x * wgt; acc.w += p1.y * wgt;
        }
    }
    for (; i < ie; i++) {
        int2 ed = g_edge[i];
        float wgt = __int_as_float(ed.y);
        uint2 v = __ldg(&Hh[(size_t)ed.x * 32 + lane]);
        float2 p0 = __half22float2(*(__half2*)&v.x);
        float2 p1 = __half22float2(*(__half2*)&v.y);
        acc.x += p0.x * wgt; acc.y += p0.y * wgt;
        acc.z += p1.x * wgt; acc.w += p1.y * wgt;
    }

    float4 b4 = ((const float4*)bias)[lane];
    acc.x = fmaxf(acc.x + b4.x, 0.0f);
    acc.y = fmaxf(acc.y + b4.y, 0.0f);
    acc.z = fmaxf(acc.z + b4.z, 0.0f);
    acc.w = fmaxf(acc.w + b4.w, 0.0f);

    if (LN) {
        float s1 = acc.x + acc.y + acc.z + acc.w;
#pragma unroll
        for (int o = 16; o > 0; o >>= 1)
            s1 += __shfl_xor_sync(0xffffffffu, s1, o);
        float mu = s1 * (1.0f / 128.0f);
        float dx = acc.x - mu, dy = acc.y - mu, dz = acc.z - mu, dw = acc.w - mu;
        float s2 = dx * dx + dy * dy + dz * dz + dw * dw;
#pragma unroll
        for (int o = 16; o > 0; o >>= 1)
            s2 += __shfl_xor_sync(0xffffffffu, s2, o);
        float r = rsqrtf(s2 * (1.0f / 128.0f) + 1e-5f);
        float4 g4  = ((const float4*)gamma)[lane];
        float4 be4 = ((const float4*)beta)[lane];
        acc.x = dx * r * g4.x + be4.x;
        acc.y = dy * r * g4.y + be4.y;
        acc.z = dz * r * g4.z + be4.z;
        acc.w = dw * r * g4.w + be4.w;
        ((float4*)outp)[w * 32 + lane] = acc;
    } else {
        ((float4*)g_G)[w * 32 + lane] = acc;
    }
}

// ---------------- launch ------------------------------------------------------
extern "C" void kernel_launch(void* const* d_in, const int* in_sizes, int n_in,
                              void* d_out, int out_size) {
    const float* x   = (const float*)d_in[0];
    const void*  ei  = d_in[1];
    const float* ea  = (const float*)d_in[2];
    const float* W1  = (const float*)d_in[3];
    const float* b1  = (const float*)d_in[4];
    const float* W2  = (const float*)d_in[5];
    const float* b2  = (const float*)d_in[6];
    const float* lng = (const float*)d_in[7];
    const float* lnb = (const float*)d_in[8];

    int n = in_sizes[0] / D;   // 40000
    int e = in_sizes[2];       // 640000

    int eb = (e + 255) / 256;

    const int WF_BYTES = 16 * 16 * 32 * 2 * 4;   // 64 KB dynamic smem
    cudaFuncSetAttribute(k_gemm<0>, cudaFuncAttributeMaxDynamicSharedMemorySize, WF_BYTES);
    cudaFuncSetAttribute(k_gemm<1>, cudaFuncAttributeMaxDynamicSharedMemorySize, WF_BYTES);

    // CSR build: deg/cnt start at zero (module load or k_scan's reset last call)
    k_deg<<<eb, 256>>>(ei, ea, e);
    k_scan<<<1, 1024>>>(n);
    k_fill<<<eb, 256>>>(ei, ea, e);

    int gemm_blocks = (n + 127) / 128;
    int agg_blocks  = (n * 32 + 255) / 256;

    k_gemm<0><<<gemm_blocks, 256, WF_BYTES>>>(x, W1, n);
    k_agg<0><<<agg_blocks, 256>>>(b1, nullptr, nullptr, nullptr, n);
    k_gemm<1><<<gemm_blocks, 256, WF_BYTES>>>(nullptr, W2, n);
    k_agg<1><<<agg_blocks, 256>>>(b2, lng, lnb, (float*)d_out, n);
}

// round 16
// speedup vs baseline: 1.3170x; 1.3170x over previous
#include <cuda_runtime.h>
#include <cuda_fp16.h>

#define D 128
#define MAXN 40000
#define MAXE 640000

// ---------------- scratch (static device globals; no allocation) -------------
__device__ float g_deg[MAXN];
__device__ int   g_cnt[MAXN];
__device__ int   g_offs[MAXN + 1];
__device__ int   g_cursor[MAXN];
__device__ __align__(16) int2   g_edge[MAXE];      // {src, nrm bits}
__device__ __align__(16) __half g_Hh[MAXN * D];    // h = A @ W, fp16 (gathered)
__device__ __align__(16) float  g_G[MAXN * D];     // post-agg activations (fp32)
__device__ int   g_is64;                           // edge_index dtype flag

// ---------------- tf32 helpers -------------------------------------------------
__device__ __forceinline__ unsigned f2tf32(float x) {
    unsigned r;
    asm("cvt.rna.tf32.f32 %0, %1;" : "=r"(r) : "f"(x));
    return r;
}
__device__ __forceinline__ void mma_tf32(float* c, const unsigned* a,
                                         unsigned b0, unsigned b1) {
    asm volatile(
        "mma.sync.aligned.m16n8k8.row.col.f32.tf32.tf32.f32 "
        "{%0,%1,%2,%3}, {%4,%5,%6,%7}, {%8,%9}, {%0,%1,%2,%3};\n"
        : "+f"(c[0]), "+f"(c[1]), "+f"(c[2]), "+f"(c[3])
        : "r"(a[0]), "r"(a[1]), "r"(a[2]), "r"(a[3]), "r"(b0), "r"(b1));
}

// ---------------- init + dtype probe (R13 proven) ------------------------------
__global__ void k_init(const void* __restrict__ ei, int n) {
    int i = blockIdx.x * blockDim.x + threadIdx.x;
    if (i < n) { g_deg[i] = 1.0f; g_cnt[i] = 0; }   // 1.0 = self-loop weight
    if (blockIdx.x == 0) {
        const long long* p = (const long long*)ei;
        bool bad = false;
        for (int j = threadIdx.x; j < 1024; j += blockDim.x) {
            long long v = p[j];
            if (v < 0 || v >= MAXN) bad = true;
        }
        bad = __syncthreads_or(bad);
        if (threadIdx.x == 0) g_is64 = bad ? 0 : 1;
    }
}

__device__ __forceinline__ int edge_at(const void* ei, long long idx) {
    if (g_is64) return (int)((const long long*)ei)[idx];
    return ((const int*)ei)[idx];
}

__global__ void k_deg(const void* __restrict__ ei,
                      const float* __restrict__ ea, int e) {
    int i = blockIdx.x * blockDim.x + threadIdx.x;
    if (i < e) {
        int dst = edge_at(ei, (long long)e + i);
        atomicAdd(&g_deg[dst], ea[i]);
        atomicAdd(&g_cnt[dst], 1);
    }
}

// Single-block exclusive scan of g_cnt -> g_offs / g_cursor (n <= 40960)
__global__ void k_scan(int n) {
    __shared__ int s[1024];
    int t = threadIdx.x;
    int ch = (n + 1023) >> 10;
    int base = t * ch;
    int sum = 0;
    for (int j = 0; j < ch; j++) {
        int idx = base + j;
        if (idx < n) sum += g_cnt[idx];
    }
    s[t] = sum;
    __syncthreads();
    for (int off = 1; off < 1024; off <<= 1) {
        int v = (t >= off) ? s[t - off] : 0;
        __syncthreads();
        s[t] += v;
        __syncthreads();
    }
    if (t == 1023) g_offs[n] = s[1023];
    int prefix = (t == 0) ? 0 : s[t - 1];
    for (int j = 0; j < ch; j++) {
        int idx = base + j;
        if (idx < n) {
            g_offs[idx]   = prefix;
            g_cursor[idx] = prefix;
            prefix += g_cnt[idx];
        }
    }
}

// int2-packed edge record (R13 proven)
__global__ void k_fill(const void* __restrict__ ei,
                       const float* __restrict__ ea, int e) {
    int i = blockIdx.x * blockDim.x + threadIdx.x;
    if (i < e) {
        int src = edge_at(ei, i);
        int dst = edge_at(ei, (long long)e + i);
        float nrm = rsqrtf(g_deg[src]) * ea[i] * rsqrtf(g_deg[dst]);
        int pos = atomicAdd(&g_cursor[dst], 1);
        g_edge[pos] = make_int2(src, __float_as_int(nrm));
    }
}

// ---------------- tf32 tensor-core GEMM, N-split for occupancy ---------------
// Block = 128 rows x 64 cols (blockIdx.y selects column half). W fragments in
// 32KB smem -> ~4 blocks/SM (was 1 at 64KB), 8 warps/SMSP hides LDS+mma chains.
template <int USE_G>
__global__ void __launch_bounds__(256) k_gemm(const float* __restrict__ Ain,
                                              const float* __restrict__ W,
                                              int nrows) {
    const float* __restrict__ A = USE_G ? (const float*)g_G : Ain;
    extern __shared__ unsigned wf[];   // [ks16][nf8][lane32][2] tf32 (32KB)

    int tid = threadIdx.x;
    int ncol0 = blockIdx.y * 64;
    // W -> tf32 fragment layout. slot s = (ks*8 + nf)*32 + lane.
    for (int s = tid; s < 16 * 8 * 32; s += 256) {
        int lane = s & 31;
        int nf = (s >> 5) & 7;
        int ks = s >> 8;
        int k = ks * 8 + (lane & 3);
        int nn = ncol0 + nf * 8 + (lane >> 2);
        unsigned lo = f2tf32(W[k * D + nn]);
        unsigned hi = f2tf32(W[(k + 4) * D + nn]);
        *(uint2*)&wf[s * 2] = make_uint2(lo, hi);
    }
    __syncthreads();

    int wid = tid >> 5, lane = tid & 31;
    int ly = lane >> 2, lx = lane & 3;
    int rowbase = blockIdx.x * 128 + wid * 16;
    int ra = rowbase + ly;     if (ra >= nrows) ra = nrows - 1;
    int rb = rowbase + ly + 8; if (rb >= nrows) rb = nrows - 1;
    const float* pa = A + (size_t)ra * D + lx;
    const float* pb = A + (size_t)rb * D + lx;

    float acc[8][4];
#pragma unroll
    for (int nf = 0; nf < 8; nf++)
#pragma unroll
        for (int j = 0; j < 4; j++) acc[nf][j] = 0.0f;

    unsigned a_cur[4], a_nxt[4];
    a_cur[0] = f2tf32(pa[0]); a_cur[1] = f2tf32(pb[0]);
    a_cur[2] = f2tf32(pa[4]); a_cur[3] = f2tf32(pb[4]);

#pragma unroll
    for (int ks = 0; ks < 16; ks++) {
        if (ks < 15) {
            int k0 = (ks + 1) * 8;
            a_nxt[0] = f2tf32(pa[k0]);     a_nxt[1] = f2tf32(pb[k0]);
            a_nxt[2] = f2tf32(pa[k0 + 4]); a_nxt[3] = f2tf32(pb[k0 + 4]);
        }
        const unsigned* wrow = &wf[(ks * 256 + lane) * 2];
#pragma unroll
        for (int nf = 0; nf < 8; nf++) {
            uint2 b = *(const uint2*)&wrow[nf * 64];
            mma_tf32(acc[nf], a_cur, b.x, b.y);
        }
#pragma unroll
        for (int j = 0; j < 4; j++) a_cur[j] = a_nxt[j];
    }

    // epilogue: pack pairs to half2. c0,c1 -> (r1, 2lx..+1); c2,c3 -> r2.
    int r1 = rowbase + ly;
    int r2 = rowbase + ly + 8;
#pragma unroll
    for (int nf = 0; nf < 8; nf++) {
        int c = ncol0 + nf * 8 + lx * 2;
        if (r1 < nrows)
            *(__half2*)&g_Hh[(size_t)r1 * D + c] = __floats2half2_rn(acc[nf][0], acc[nf][1]);
        if (r2 < nrows)
            *(__half2*)&g_Hh[(size_t)r2 * D + c] = __floats2half2_rn(acc[nf][2], acc[nf][3]);
    }
}

// ---------------- aggregation (R13 proven): warp/node, fp16 gather, 8-unroll --
template <int LN>
__global__ void k_agg(const float* __restrict__ bias,
                      const float* __restrict__ gamma, const float* __restrict__ beta,
                      float* __restrict__ outp, int n) {
    int w = (blockIdx.x * blockDim.x + threadIdx.x) >> 5;
    int lane = threadIdx.x & 31;
    if (w >= n) return;

    const uint2* __restrict__ Hh = (const uint2*)g_Hh;   // 32 uint2 per row
    float di = rsqrtf(g_deg[w]);
    float selfw = di * di;

    uint2 vs = __ldg(&Hh[(size_t)w * 32 + lane]);
    float2 s0f = __half22float2(*(__half2*)&vs.x);
    float2 s1f = __half22float2(*(__half2*)&vs.y);
    float4 acc = make_float4(s0f.x * selfw, s0f.y * selfw,
                             s1f.x * selfw, s1f.y * selfw);

    int ib = g_offs[w];
    int ie = g_offs[w + 1];
    int i = ib;
    for (; i + 8 <= ie; i += 8) {
        int2 ed[8];
        uint2 v[8];
#pragma unroll
        for (int j = 0; j < 8; j++) ed[j] = g_edge[i + j];
#pragma unroll
        for (int j = 0; j < 8; j++)
            v[j] = __ldg(&Hh[(size_t)ed[j].x * 32 + lane]);
#pragma unroll
        for (int j = 0; j < 8; j++) {
            float wgt = __int_as_float(ed[j].y);
            float2 p0 = __half22float2(*(__half2*)&v[j].x);
            float2 p1 = __half22float2(*(__half2*)&v[j].y);
            acc.x += p0.x * wgt; acc.y += p0.y * wgt;
            acc.z += p1.x * wgt; acc.w += p1.y * wgt;
        }
    }
    for (; i < ie; i++) {
        int2 ed = g_edge[i];
        float wgt = __int_as_float(ed.y);
        uint2 v = __ldg(&Hh[(size_t)ed.x * 32 + lane]);
        float2 p0 = __half22float2(*(__half2*)&v.x);
        float2 p1 = __half22float2(*(__half2*)&v.y);
        acc.x += p0.x * wgt; acc.y += p0.y * wgt;
        acc.z += p1.x * wgt; acc.w += p1.y * wgt;
    }

    float4 b4 = ((const float4*)bias)[lane];
    acc.x = fmaxf(acc.x + b4.x, 0.0f);
    acc.y = fmaxf(acc.y + b4.y, 0.0f);
    acc.z = fmaxf(acc.z + b4.z, 0.0f);
    acc.w = fmaxf(acc.w + b4.w, 0.0f);

    if (LN) {
        float s1 = acc.x + acc.y + acc.z + acc.w;
#pragma unroll
        for (int o = 16; o > 0; o >>= 1)
            s1 += __shfl_xor_sync(0xffffffffu, s1, o);
        float mu = s1 * (1.0f / 128.0f);
        float dx = acc.x - mu, dy = acc.y - mu, dz = acc.z - mu, dw = acc.w - mu;
        float s2 = dx * dx + dy * dy + dz * dz + dw * dw;
#pragma unroll
        for (int o = 16; o > 0; o >>= 1)
            s2 += __shfl_xor_sync(0xffffffffu, s2, o);
        float r = rsqrtf(s2 * (1.0f / 128.0f) + 1e-5f);
        float4 g4  = ((const float4*)gamma)[lane];
        float4 be4 = ((const float4*)beta)[lane];
        acc.x = dx * r * g4.x + be4.x;
        acc.y = dy * r * g4.y + be4.y;
        acc.z = dz * r * g4.z + be4.z;
        acc.w = dw * r * g4.w + be4.w;
        ((float4*)outp)[w * 32 + lane] = acc;
    } else {
        ((float4*)g_G)[w * 32 + lane] = acc;
    }
}

// ---------------- launch ------------------------------------------------------
extern "C" void kernel_launch(void* const* d_in, const int* in_sizes, int n_in,
                              void* d_out, int out_size) {
    const float* x   = (const float*)d_in[0];
    const void*  ei  = d_in[1];
    const float* ea  = (const float*)d_in[2];
    const float* W1  = (const float*)d_in[3];
    const float* b1  = (const float*)d_in[4];
    const float* W2  = (const float*)d_in[5];
    const float* b2  = (const float*)d_in[6];
    const float* lng = (const float*)d_in[7];
    const float* lnb = (const float*)d_in[8];

    int n = in_sizes[0] / D;   // 40000
    int e = in_sizes[2];       // 640000

    int nb = (n + 255) / 256;
    int eb = (e + 255) / 256;

    const int WF_BYTES = 16 * 8 * 32 * 2 * 4;   // 32 KB dynamic smem
    cudaFuncSetAttribute(k_gemm<0>, cudaFuncAttributeMaxDynamicSharedMemorySize, WF_BYTES);
    cudaFuncSetAttribute(k_gemm<1>, cudaFuncAttributeMaxDynamicSharedMemorySize, WF_BYTES);

    k_init<<<nb, 256>>>(ei, n);
    k_deg<<<eb, 256>>>(ei, ea, e);
    k_scan<<<1, 1024>>>(n);
    k_fill<<<eb, 256>>>(ei, ea, e);

    dim3 gemm_grid((n + 127) / 128, 2);
    int agg_blocks = (n * 32 + 255) / 256;

    k_gemm<0><<<gemm_grid, 256, WF_BYTES>>>(x, W1, n);
    k_agg<0><<<agg_blocks, 256>>>(b1, nullptr, nullptr, nullptr, n);
    k_gemm<1><<<gemm_grid, 256, WF_BYTES>>>(nullptr, W2, n);
    k_agg<1><<<agg_blocks, 256>>>(b2, lng, lnb, (float*)d_out, n);
}